// round 12
// baseline (speedup 1.0000x reference)
#include <cuda_runtime.h>

#define CC 8
#define NN 4096
#define NC (CC*NN)
#define KH 11
#define MAXDET 100
#define XBINS 768          // x1 in [-64, 704), 1px bins
#define XOFF 64
#define K1_TILE 32
#define K1_SUB 16
#define K1_SPAN 1024
#define TILES_PC 128
#define NJOBS (CC*TILES_PC)   // 1024
#define BID_B0 CC             // 8
#define NBLK_AB (CC + NJOBS)  // 1032
#define TOPK_PC 128           // per-class published top keys

// ---------------- scratch (device globals; no allocation) ----------------
__device__ int    g_m[CC];            // valid count per class
__device__ float4 g_sbox[NC];         // bin-sorted boxes (by slot)
__device__ float2 g_saux[NC];         // sorted aux: (area, orig idx as int bits)
__device__ int    g_rmin[NC];         // per sorted slot: min orig idx of hit (init self)
__device__ float  g_val[NC];          // per-slot candidate value (phase1)
__device__ int    g_maxcol[NC];       // per-slot winning row (phase1)
__device__ int    g_candcnt[NC];      // per-row candidate counts (zeroed by kC after read)
__device__ float  g_pavg[NC*12];
__device__ float  g_bavg[NC*4];
__device__ int    g_scount[CC];       // survivors per class
__device__ int    g_srow[NC];         // compacted survivor rows (ascending per class)
__device__ unsigned g_skey[NC];       // compacted survivor keys (monotone score bits)
__device__ unsigned g_top[CC*TOPK_PC]; // per-class top-128 keys (desc)
__device__ int    g_sync;             // last-class-block counter (reset by last kC block)
__device__ int    g_fA[CC];           // stage-A done flags (reset by last kC block)
__device__ int    g_fB[CC];           // stage-B completion counters (reset by last kC block)

// ---------------- shuffle-based inclusive block scan ----------------
__device__ __forceinline__ int blockScanInc(int v, int* ws) {
    const unsigned FULL = 0xFFFFFFFFu;
    int lane = threadIdx.x & 31, w = threadIdx.x >> 5;
    int nw = blockDim.x >> 5;
#pragma unroll
    for (int o = 1; o < 32; o <<= 1) {
        int n = __shfl_up_sync(FULL, v, o);
        if (lane >= o) v += n;
    }
    if (lane == 31) ws[w] = v;
    __syncthreads();
    if (w == 0) {
        int s = (lane < nw) ? ws[lane] : 0;
#pragma unroll
        for (int o = 1; o < 32; o <<= 1) {
            int n = __shfl_up_sync(FULL, s, o);
            if (lane >= o) s += n;
        }
        if (lane < nw) ws[lane] = s;
    }
    __syncthreads();
    int r = v + ((w > 0) ? ws[w - 1] : 0);
    __syncthreads();
    return r;
}

// ---------------- stage A: per-class compact + counting sort (512 threads) ----------------
__device__ void stageA(int c, const float* __restrict__ cls,
                       const float* __restrict__ boxes, int* sm, int* ws) {
    int* hist   = sm;            // [XBINS]
    int* sstart = sm + XBINS;    // [XBINS]
    int t = threadIdx.x;

    for (int b = t; b < XBINS; b += 512) hist[b] = 0;
    __syncthreads();

    int mybin[8];
#pragma unroll
    for (int u = 0; u < 8; u++) {
        int a = t + u * 512;
        float sc = cls[a * CC + c];
        if (sc > 0.5f) {
            float x1 = boxes[(size_t)a * (CC * 4) + c * 4];
            int b = __float2int_rd(x1) + XOFF;
            b = max(0, min(XBINS - 1, b));
            mybin[u] = b;
            atomicAdd(&hist[b], 1);
        } else {
            mybin[u] = -1;
        }
    }
    __syncthreads();

    int h0 = (2 * t < XBINS) ? hist[2 * t] : 0;
    int h1 = (2 * t + 1 < XBINS) ? hist[2 * t + 1] : 0;
    int run = h0 + h1;
    int inc = blockScanInc(run, ws);
    int base = inc - run;
    if (2 * t < XBINS) sstart[2 * t] = base;
    if (2 * t + 1 < XBINS) sstart[2 * t + 1] = base + h0;
    if (t == 511) g_m[c] = inc;
    __syncthreads();
    for (int b = t; b < XBINS; b += 512) hist[b] = 0;
    __syncthreads();

#pragma unroll
    for (int u = 0; u < 8; u++) {
        if (mybin[u] >= 0) {
            int a = t + u * 512;
            float4 b = *(const float4*)(boxes + (size_t)a * (CC * 4) + c * 4);
            int pos = sstart[mybin[u]] + atomicAdd(&hist[mybin[u]], 1);
            int slot = c * NN + pos;
            g_sbox[slot] = b;
            g_saux[slot] = make_float2((b.z - b.x + 1.0f) * (b.w - b.y + 1.0f),
                                       __int_as_float(a));
            g_rmin[slot] = a;   // self hit baseline
        }
    }
}

// ---------------- stage B: one k1 job (512 threads) ----------------
__device__ void stageB(int job, int* sm) {
    float4* tb = (float4*)sm;                // [K1_SPAN]
    float2* ta = (float2*)(tb + K1_SPAN);    // [K1_SPAN]
    int t = threadIdx.x;

    int c  = job >> 7;
    int S0 = (job & (TILES_PC - 1)) * K1_TILE;
    int m  = g_m[c];
    if (S0 >= m) return;

    for (int k = t; k < K1_SPAN; k += 512) {
        int s = S0 + k;
        if (s < m) {
            tb[k] = g_sbox[c * NN + s];
            ta[k] = g_saux[c * NN + s];
        } else {
            tb[k] = make_float4(3.0e38f, 0.0f, -10.0f, -10.0f);
            ta[k] = make_float2(1.0f, __int_as_float(0));
        }
    }
    __syncthreads();

    int ai  = t & (K1_TILE - 1);
    int sub = t >> 5;      // 0..15
    int s = S0 + ai;
    if (s >= m) return;

    float4 a    = tb[ai];
    float areaA = ta[ai].x;
    int   origI = __float_as_int(ta[ai].y);
    float limit = a.z + 2.0f;   // (x2_s + 1) + 1px bin-order slop

    for (int ts = ai + 1 + sub; ; ts += K1_SUB) {
        float4 b;
        bool glob = false;
        int gs = 0;
        if (ts < K1_SPAN) {
            b = tb[ts];
        } else {
            gs = S0 + ts;
            if (gs >= m) break;
            b = g_sbox[c * NN + gs];
            glob = true;
        }
        if (b.x >= limit) break;

        float x1 = fmaxf(a.x, b.x);
        float y1 = fmaxf(a.y, b.y);
        float x2 = fminf(a.z, b.z);
        float y2 = fminf(a.w, b.w);
        float w = x2 - x1 + 1.0f;
        float h = y2 - y1 + 1.0f;
        if (w > 0.0f && h > 0.0f) {
            float inter = w * h;
            float2 ax = glob ? g_saux[c * NN + gs] : ta[ts];
            float den = areaA + ax.x - inter;
            if (inter > 0.5f * den) {
                int origJ = __float_as_int(ax.y);
                atomicMin(&g_rmin[c * NN + s], origJ);
                atomicMin(&g_rmin[c * NN + S0 + ts], origI);
            }
        }
    }
}

// ---------------- phase 1: per-slot winner values + global row counts (512 threads) ----------------
__device__ void phase1(int c, const float* __restrict__ boxes,
                       const float* __restrict__ conf) {
    int t = threadIdx.x;
    int m = g_m[c];
#pragma unroll
    for (int u = 0; u < 8; u++) {
        int s = t + u * 512;
        if (s >= m) break;
        int slot = c * NN + s;
        int r = g_rmin[slot];
        int i = __float_as_int(g_saux[slot].y);
        float v = 0.0f;
        if (r != i) {
            float4 bi = g_sbox[slot];
            float4 br = *(const float4*)(boxes + (size_t)r * (CC * 4) + c * 4);
            float x1 = fmaxf(bi.x, br.x);
            float y1 = fmaxf(bi.y, br.y);
            float x2 = fminf(bi.z, br.z);
            float y2 = fminf(bi.w, br.w);
            float w = x2 - x1 + 1.0f;
            float h = y2 - y1 + 1.0f;
            float inter = w * h;
            float areaI = (bi.z - bi.x + 1.0f) * (bi.w - bi.y + 1.0f);
            float areaR = (br.z - br.x + 1.0f) * (br.w - br.y + 1.0f);
            float den = areaI + areaR - inter;
            float ov = (den == 0.0f) ? 0.0f : inter / den;
            if (w <= 0.0f || h <= 0.0f) ov = 0.0f;
            v = (1.0f - ov) * conf[i * CC + c];
            if (v != 0.0f) atomicAdd(&g_candcnt[c * NN + r], 1);
        }
        g_val[slot] = v;
        g_maxcol[slot] = r;
    }
}

// ---------------- kernel AB ----------------
__global__ __launch_bounds__(512) void kAB(const float* __restrict__ cls,
                                           const float* __restrict__ boxes,
                                           const float* __restrict__ conf) {
    extern __shared__ int sm[];
    __shared__ int ws[16];
    __shared__ int do_p1;
    int bid = blockIdx.x;

    if (bid < CC) {
        stageA(bid, cls, boxes, sm, ws);
        __syncthreads();
        if (threadIdx.x == 0) {
            __threadfence();
            atomicExch(&g_fA[bid], 1);
        }
    } else {
        int job = bid - BID_B0;
        int c = job >> 7;
        if (threadIdx.x == 0) {
            while (atomicAdd(&g_fA[c], 0) == 0) { __nanosleep(128); }
            __threadfence();
        }
        __syncthreads();
        stageB(job, sm);
        __syncthreads();
        if (threadIdx.x == 0) {
            __threadfence();
            int old = atomicAdd(&g_fB[c], 1);
            do_p1 = (old == TILES_PC - 1) ? 1 : 0;
            if (do_p1) __threadfence();
        }
        __syncthreads();
        if (do_p1) phase1(c, boxes, conf);   // last B block of class: values off kC's path
    }
}

// ---------------- kernel C: scan+scatter+top-11+compaction+class-sort, last block merges ----------------
// smem: scnt[4096] | soff[4096] | cand[4096] u64   (sort reuses scnt region as u32[4096])
__global__ __launch_bounds__(1024) void kC(const float* __restrict__ boxes,
                                           const float* __restrict__ poses,
                                           const float* __restrict__ cls,
                                           float* __restrict__ out, int out_size) {
    extern __shared__ int sm[];
    int* scnt = sm;                    // cursors / sort buffer
    int* soff = sm + NN;               // exclusive offsets
    unsigned long long* cand = (unsigned long long*)(sm + 2 * NN);
    __shared__ int ws[32];
    __shared__ int is_last, m_surv;

    int c = blockIdx.x;
    int t = threadIdx.x;
    int m = g_m[c];

    // --- phase 2: read row counts (+ zero them globally for next launch), scan ---
    int4 cnt4 = *(const int4*)&g_candcnt[c * NN + t * 4];
    *(int4*)&g_candcnt[c * NN + t * 4] = make_int4(0, 0, 0, 0);
    int rcnt[4] = {cnt4.x, cnt4.y, cnt4.z, cnt4.w};
    int run = rcnt[0] + rcnt[1] + rcnt[2] + rcnt[3];
    int incv = blockScanInc(run, ws);
    int base = incv - run;
    {
        int acc = base;
#pragma unroll
        for (int u = 0; u < 4; u++) { soff[t * 4 + u] = acc; acc += rcnt[u]; }
    }
    *(int4*)&scnt[t * 4] = make_int4(0, 0, 0, 0);
    __syncthreads();

    // --- phase 3: scatter candidates into smem CSR ---
#pragma unroll
    for (int u = 0; u < 4; u++) {
        int s = t + u * 1024;
        if (s < m) {
            int slot = c * NN + s;
            float v = g_val[slot];
            if (v != 0.0f) {
                int r = g_maxcol[slot];
                int i = __float_as_int(g_saux[slot].y);
                int pos = soff[r] + atomicAdd(&scnt[r], 1);
                cand[pos] = ((unsigned long long)__float_as_uint(v) << 32) | (unsigned)i;
            }
        }
    }
    __syncthreads();

    // --- phase 4: per-row top-11 + averages ---
    int L = min(KH, m);
    bool survu[4];
#pragma unroll
    for (int u = 0; u < 4; u++) {
        int row = t * 4 + u;
        int cnt = rcnt[u];
        int used = 0;
        if (cnt > 0) {
            int off = soff[row];
            unsigned long long b[KH];
#pragma unroll
            for (int p = 0; p < KH; p++) b[p] = ~0ULL;
            for (int q = 0; q < cnt; q++) {
                unsigned long long x = cand[off + q];
#pragma unroll
                for (int p = 0; p < KH; p++) {
                    unsigned long long lo = (b[p] < x) ? b[p] : x;
                    unsigned long long hi = (b[p] < x) ? x : b[p];
                    b[p] = lo;
                    x = hi;
                }
            }
            used = min(min(cnt, KH), L);
            if (used > 0) {
                float ps[12], bs4[4];
#pragma unroll
                for (int d = 0; d < 12; d++) ps[d] = 0.0f;
#pragma unroll
                for (int d = 0; d < 4; d++) bs4[d] = 0.0f;
                for (int q = 0; q < used; q++) {
                    int a = (int)(b[q] & 0xFFFFFFFFu);
                    const float* pp = poses + (size_t)a * (CC * 12) + c * 12;
#pragma unroll
                    for (int d = 0; d < 12; d++) ps[d] += pp[d];
                    const float* bx = boxes + (size_t)a * (CC * 4) + c * 4;
#pragma unroll
                    for (int d = 0; d < 4; d++) bs4[d] += bx[d];
                }
                float den = (float)used;
                int grow = c * NN + row;
#pragma unroll
                for (int d = 0; d < 12; d++) g_pavg[grow * 12 + d] = ps[d] / den;
#pragma unroll
                for (int d = 0; d < 4; d++) g_bavg[grow * 4 + d] = bs4[d] / den;
            }
        }
        survu[u] = (used > 0);
    }
    __syncthreads();

    // --- phase 5: survivor compaction (rows ascending) + key build ---
    int srun = 0;
    int spre[4];
#pragma unroll
    for (int u = 0; u < 4; u++) {
        spre[u] = srun;
        srun += survu[u] ? 1 : 0;
    }
    int sinc = blockScanInc(srun, ws);
    int sbase = sinc - srun;
#pragma unroll
    for (int u = 0; u < 4; u++) {
        if (survu[u]) {
            int row = t * 4 + u;
            int pos = sbase + spre[u];
            g_srow[c * NN + pos] = row;
            unsigned ub = __float_as_uint(cls[row * CC + c]);
            g_skey[c * NN + pos] = ub ^ ((ub & 0x80000000u) ? 0xFFFFFFFFu : 0x80000000u);
        }
    }
    if (t == 1023) { g_scount[c] = sinc; m_surv = sinc; }
    __syncthreads();
    int Sc = m_surv;

    // --- phase 6: per-class bitonic sort (desc) of survivor keys, publish top-128 ---
    unsigned* srt = (unsigned*)scnt;   // 4096 u32 (reuses scnt+soff region? no: scnt only = 4096 ints)
#pragma unroll
    for (int u = 0; u < 4; u++) {
        int q = t + u * 1024;
        srt[q] = (q < Sc) ? g_skey[c * NN + q] : 0u;
    }
    __syncthreads();
    for (int k = 2; k <= 4096; k <<= 1) {
        for (int j = k >> 1; j > 0; j >>= 1) {
#pragma unroll
            for (int e = t; e < 2048; e += 1024) {
                int i = 2 * e - (e & (j - 1));
                int p = i + j;
                unsigned A = srt[i], B = srt[p];
                bool up = ((i & k) == 0);
                if ((A < B) == up) { srt[i] = B; srt[p] = A; }   // descending
            }
            __syncthreads();
        }
    }
    if (t < TOPK_PC) g_top[c * TOPK_PC + t] = srt[t];
    __syncthreads();

    // --- phase 7: last block merges + writes all outputs ---
    if (t == 0) {
        __threadfence();
        int old = atomicAdd(&g_sync, 1);
        is_last = (old == CC - 1) ? 1 : 0;
        if (is_last) __threadfence();
    }
    __syncthreads();
    if (!is_last) return;

    __shared__ int cb[CC + 1];
    __shared__ int sel[MAXDET];
    if (t == 0) {
        int s = 0;
        for (int cc2 = 0; cc2 < CC; cc2++) { cb[cc2] = s; s += g_scount[cc2]; }
        cb[CC] = s;
    }
    __syncthreads();
    int S = cb[CC];

    if (t < MAXDET && t < S) {
        int cc2 = 0;
        while (cc2 < CC - 1 && t >= cb[cc2 + 1]) cc2++;
        sel[t] = cc2 * NN + g_srow[cc2 * NN + (t - cb[cc2])];
    }

    // merge 8*128 = 1024 keys, bitonic desc
    if (t < CC * TOPK_PC) srt[t] = g_top[t];
    __syncthreads();
    for (int k = 2; k <= 1024; k <<= 1) {
        for (int j = k >> 1; j > 0; j >>= 1) {
            if (t < 512) {
                int e = t;
                int i = 2 * e - (e & (j - 1));
                int p = i + j;
                unsigned A = srt[i], B = srt[p];
                bool up = ((i & k) == 0);
                if ((A < B) == up) { srt[i] = B; srt[p] = A; }
            }
            __syncthreads();
        }
    }

    // outputs: [scores 100][labels 100][poses 1200][idx 100][boxes 400] = 1900 floats
    if (t < MAXDET) {
        int q = t;
        float osc = -1.0f;
        if (q < S) {
            unsigned u = srt[q];
            u = (u & 0x80000000u) ? (u ^ 0x80000000u) : ~u;
            osc = __uint_as_float(u);
        }
        if (q < out_size) out[q] = osc;
        float lab = (q < S) ? (float)(sel[q] >> 12) : -1.0f;
        if (100 + q < out_size) out[100 + q] = lab;
        float idx = (q < S) ? (float)(sel[q] & (NN - 1)) : -1.0f;
        if (1400 + q < out_size) out[1400 + q] = idx;
    }
    for (int q = t; q < 1200; q += 1024) {
        int k = q / 12, d = q % 12;
        float v = (k < S) ? g_pavg[sel[k] * 12 + d] : -1.0f;
        if (200 + q < out_size) out[200 + q] = v;
    }
    for (int q = t; q < 400; q += 1024) {
        int k = q >> 2, d = q & 3;
        float v = (k < S) ? g_bavg[sel[k] * 4 + d] : -1.0f;
        if (1500 + q < out_size) out[1500 + q] = v;
    }
    __syncthreads();
    // reset coordination state for the next graph replay
    if (t < CC) { g_fA[t] = 0; g_fB[t] = 0; }
    if (t == 0) g_sync = 0;
}

// ---------------- launcher ----------------
extern "C" void kernel_launch(void* const* d_in, const int* in_sizes, int n_in,
                              void* d_out, int out_size) {
    (void)in_sizes; (void)n_in;
    const float* boxes = (const float*)d_in[1];
    const float* cls   = (const float*)d_in[2];
    const float* poses = (const float*)d_in[3];
    const float* conf  = (const float*)d_in[4];
    float* out = (float*)d_out;

    int smemAB = K1_SPAN * (int)(sizeof(float4) + sizeof(float2));   // 24KB
    int smemC  = 2 * NN * (int)sizeof(int) + NN * (int)sizeof(unsigned long long) + 128;
    cudaFuncSetAttribute(kAB, cudaFuncAttributeMaxDynamicSharedMemorySize, smemAB);
    cudaFuncSetAttribute(kC, cudaFuncAttributeMaxDynamicSharedMemorySize, smemC);

    kAB<<<NBLK_AB, 512, smemAB>>>(cls, boxes, conf);
    kC<<<CC, 1024, smemC>>>(boxes, poses, cls, out, out_size);
}

// round 14
// speedup vs baseline: 1.2669x; 1.2669x over previous
#include <cuda_runtime.h>

#define CC 8
#define NN 4096
#define NC (CC*NN)
#define KH 11
#define MAXDET 100
#define XBINS 768          // x1 in [-64, 704), 1px bins
#define XOFF 64
#define K1_TILE 32
#define K1_SUB 16
#define K1_SPAN 1024
#define TILES_PC 128

// ---------------- scratch (device globals; no allocation) ----------------
__device__ int    g_m[CC];            // valid count per class
__device__ float4 g_sbox[NC];         // bin-sorted boxes (by slot)
__device__ float2 g_saux[NC];         // sorted aux: (area, orig idx as int bits)
__device__ int    g_rmin[NC];         // per sorted slot: min orig idx of hit (init self)
__device__ float  g_val[NC];          // per-slot candidate value (phase1)
__device__ int    g_maxcol[NC];       // per-slot winning row (phase1)
__device__ int    g_candcnt[NC];      // per-row candidate counts (zeroed by k2 after read)
__device__ float  g_pavg[NC*12];
__device__ float  g_bavg[NC*4];
__device__ int    g_scount[CC];       // survivors per class
__device__ int    g_srow[NC];         // compacted survivor rows (ascending per class)
__device__ unsigned g_skey[NC];       // compacted survivor keys (monotone score bits)
__device__ int    g_sync;             // last-class-block counter (reset by last k2 block)
__device__ int    g_fB[CC];           // k1 per-class completion counters (reset by last k2 block)

// ---------------- shuffle-based inclusive block scan ----------------
__device__ __forceinline__ int blockScanInc(int v, int* ws) {
    const unsigned FULL = 0xFFFFFFFFu;
    int lane = threadIdx.x & 31, w = threadIdx.x >> 5;
    int nw = blockDim.x >> 5;
#pragma unroll
    for (int o = 1; o < 32; o <<= 1) {
        int n = __shfl_up_sync(FULL, v, o);
        if (lane >= o) v += n;
    }
    if (lane == 31) ws[w] = v;
    __syncthreads();
    if (w == 0) {
        int s = (lane < nw) ? ws[lane] : 0;
#pragma unroll
        for (int o = 1; o < 32; o <<= 1) {
            int n = __shfl_up_sync(FULL, s, o);
            if (lane >= o) s += n;
        }
        if (lane < nw) ws[lane] = s;
    }
    __syncthreads();
    int r = v + ((w > 0) ? ws[w - 1] : 0);
    __syncthreads();
    return r;
}

// ---------------- K0: per-class compact + counting sort (1024 threads) ----------------
__global__ __launch_bounds__(1024) void k0_sort(const float* __restrict__ cls,
                                                const float* __restrict__ boxes) {
    __shared__ int hist[XBINS];
    __shared__ int sstart[XBINS];
    __shared__ int ws[32];
    int c = blockIdx.x;
    int t = threadIdx.x;

    if (c == 0 && t == 0) g_sync = 0;

    for (int b = t; b < XBINS; b += 1024) hist[b] = 0;
    __syncthreads();

    bool   myv[4];
    int    mybin[4];
    float4 mybox[4];
#pragma unroll
    for (int u = 0; u < 4; u++) {
        int a = t + u * 1024;
        float sc = cls[a * CC + c];
        myv[u] = sc > 0.5f;
        if (myv[u]) {
            mybox[u] = *(const float4*)(boxes + (size_t)a * (CC * 4) + c * 4);
            int b = __float2int_rd(mybox[u].x) + XOFF;
            b = max(0, min(XBINS - 1, b));
            mybin[u] = b;
            atomicAdd(&hist[b], 1);
        }
    }
    __syncthreads();

    int hv = (t < XBINS) ? hist[t] : 0;
    int inc = blockScanInc(hv, ws);
    if (t < XBINS) sstart[t] = inc - hv;
    if (t == XBINS - 1) g_m[c] = inc;
    __syncthreads();
    for (int b = t; b < XBINS; b += 1024) hist[b] = 0;
    __syncthreads();

#pragma unroll
    for (int u = 0; u < 4; u++) {
        if (myv[u]) {
            int a = t + u * 1024;
            int pos = sstart[mybin[u]] + atomicAdd(&hist[mybin[u]], 1);
            int slot = c * NN + pos;
            float4 b = mybox[u];
            g_sbox[slot] = b;
            g_saux[slot] = make_float2((b.z - b.x + 1.0f) * (b.w - b.y + 1.0f),
                                       __int_as_float(a));
            g_rmin[slot] = a;   // self hit baseline
        }
    }
}

// ---------------- phase 1: per-slot winner values + global row counts (512 threads) ----------------
__device__ void phase1(int c, const float* __restrict__ boxes,
                       const float* __restrict__ conf) {
    int t = threadIdx.x;
    int m = g_m[c];
#pragma unroll 1
    for (int u = 0; u < 8; u++) {
        int s = t + u * 512;
        if (s >= m) break;
        int slot = c * NN + s;
        int r = g_rmin[slot];
        int i = __float_as_int(g_saux[slot].y);
        float v = 0.0f;
        if (r != i) {
            float4 bi = g_sbox[slot];
            float4 br = *(const float4*)(boxes + (size_t)r * (CC * 4) + c * 4);
            float x1 = fmaxf(bi.x, br.x);
            float y1 = fmaxf(bi.y, br.y);
            float x2 = fminf(bi.z, br.z);
            float y2 = fminf(bi.w, br.w);
            float w = x2 - x1 + 1.0f;
            float h = y2 - y1 + 1.0f;
            float inter = w * h;
            float areaI = (bi.z - bi.x + 1.0f) * (bi.w - bi.y + 1.0f);
            float areaR = (br.z - br.x + 1.0f) * (br.w - br.y + 1.0f);
            float den = areaI + areaR - inter;
            float ov = (den == 0.0f) ? 0.0f : inter / den;
            if (w <= 0.0f || h <= 0.0f) ov = 0.0f;
            v = (1.0f - ov) * conf[i * CC + c];
            if (v != 0.0f) atomicAdd(&g_candcnt[c * NN + r], 1);
        }
        g_val[slot] = v;
        g_maxcol[slot] = r;
    }
}

// ---------------- K1: symmetric forward pair scan; last block/class runs phase1 ----------------
__global__ __launch_bounds__(512) void k1_pairs(const float* __restrict__ boxes,
                                                const float* __restrict__ conf) {
    __shared__ float4 tb[K1_SPAN];
    __shared__ float2 ta[K1_SPAN];
    __shared__ int do_p1;

    int c  = blockIdx.x >> 7;           // 128 tiles per class
    int S0 = (blockIdx.x & 127) * K1_TILE;
    int m  = g_m[c];
    int t  = threadIdx.x;
    bool active = (S0 < m);

    if (active) {
        for (int k = t; k < K1_SPAN; k += 512) {
            int s = S0 + k;
            if (s < m) {
                tb[k] = g_sbox[c * NN + s];
                ta[k] = g_saux[c * NN + s];
            } else {
                tb[k] = make_float4(3.0e38f, 0.0f, -10.0f, -10.0f); // x1=+inf sentinel
                ta[k] = make_float2(1.0f, __int_as_float(0));
            }
        }
    }
    __syncthreads();

    if (active) {
        int ai  = t & (K1_TILE - 1);
        int sub = t >> 5;      // 0..15
        int s = S0 + ai;
        if (s < m) {
            float4 a    = tb[ai];
            float areaA = ta[ai].x;
            int   origI = __float_as_int(ta[ai].y);
            float limit = a.z + 2.0f;   // (x2_s + 1) + 1px bin-order slop

            for (int ts = ai + 1 + sub; ; ts += K1_SUB) {
                float4 b;
                bool glob = false;
                int gs = 0;
                if (ts < K1_SPAN) {
                    b = tb[ts];
                } else {
                    gs = S0 + ts;
                    if (gs >= m) break;
                    b = g_sbox[c * NN + gs];
                    glob = true;
                }
                if (b.x >= limit) break;

                float x1 = fmaxf(a.x, b.x);
                float y1 = fmaxf(a.y, b.y);
                float x2 = fminf(a.z, b.z);
                float y2 = fminf(a.w, b.w);
                float w = x2 - x1 + 1.0f;
                float h = y2 - y1 + 1.0f;
                if (w > 0.0f && h > 0.0f) {
                    float inter = w * h;
                    float2 ax = glob ? g_saux[c * NN + gs] : ta[ts];  // deferred load
                    float den = areaA + ax.x - inter;
                    if (inter > 0.5f * den) {
                        int origJ = __float_as_int(ax.y);
                        atomicMin(&g_rmin[c * NN + s], origJ);
                        atomicMin(&g_rmin[c * NN + S0 + ts], origI);
                    }
                }
            }
        }
    }
    __syncthreads();

    // last-finishing block of this class computes winner values + row counts
    if (t == 0) {
        __threadfence();
        int old = atomicAdd(&g_fB[c], 1);
        do_p1 = (old == TILES_PC - 1) ? 1 : 0;
        if (do_p1) __threadfence();
    }
    __syncthreads();
    if (do_p1) phase1(c, boxes, conf);
}

// ---------------- find threshold bin in histogram (proven 3-pass helper) ----------------
__device__ __forceinline__ void find_thr(const int* hist, int nbins, int target,
                                         volatile int* out_b, volatile int* out_t,
                                         int* ws) {
    int t = threadIdx.x;
    if (t == 0) { *out_b = 0; *out_t = 0; }
    __syncthreads();
    if (nbins == 2048) {
        int b1 = 2047 - 2 * t;
        int b0 = b1 - 1;
        int h1 = hist[b1], h0 = hist[b0];
        int inc = blockScanInc(h1 + h0, ws);     // suffix sum at b0
        int suf0 = inc;
        int suf1 = inc - h0;
        if (suf1 >= target && suf1 - h1 < target) { *out_b = b1; *out_t = target - (suf1 - h1); }
        if (suf0 >= target && suf0 - h0 < target) { *out_b = b0; *out_t = target - (suf0 - h0); }
    } else {
        int b = 1023 - t;
        int h = hist[b];
        int inc = blockScanInc(h, ws);
        if (inc >= target && inc - h < target) { *out_b = b; *out_t = target - (inc - h); }
    }
    __syncthreads();
}

// ---------------- k5 body: proven 3-pass radix select + rank sort (register-cached keys) ----------------
__device__ void k5_body(int* hist, int* ws, float* __restrict__ out, int out_size) {
    __shared__ int cb[CC + 1];
    __shared__ int sel[MAXDET];
    __shared__ unsigned arr[MAXDET];
    __shared__ unsigned srt[MAXDET];
    __shared__ volatile int b_sh, t_sh;
    __shared__ int t1_sh, b1_sh, e_sh, gcnt, ecnt;
    __shared__ unsigned pre_sh, K100_sh;

    int t = threadIdx.x;
    if (t == 0) {
        int s = 0;
        for (int c = 0; c < CC; c++) { cb[c] = s; s += g_scount[c]; }
        cb[CC] = s;
        gcnt = 0; ecnt = 0;
    }
    __syncthreads();
    int S = cb[CC];

    if (t < MAXDET && t < S) {
        int c = 0;
        while (c < CC - 1 && t >= cb[c + 1]) c++;
        sel[t] = c * NN + g_srow[c * NN + (t - cb[c])];
    }

    // load this thread's keys once (class-contiguous)
    unsigned kk[32];
    int nk = 0;
#pragma unroll 1
    for (int c = 0; c < CC; c++) {
        int cnt = cb[c + 1] - cb[c];
        for (int q = t; q < cnt; q += 1024) kk[nk++] = g_skey[c * NN + q];
    }

    // ---- radix-select level 1 (top 11 bits) ----
    hist[t] = 0; hist[t + 1024] = 0;
    __syncthreads();
    for (int i = 0; i < nk; i++) atomicAdd(&hist[kk[i] >> 21], 1);
    __syncthreads();
    find_thr(hist, 2048, MAXDET, &b_sh, &t_sh, ws);
    if (t == 0) { b1_sh = b_sh; t1_sh = t_sh; }
    __syncthreads();
    unsigned b1 = (unsigned)b1_sh;
    int tgt2 = t1_sh;

    // ---- level 2 (next 11 bits) ----
    hist[t] = 0; hist[t + 1024] = 0;
    __syncthreads();
    for (int i = 0; i < nk; i++)
        if ((kk[i] >> 21) == b1) atomicAdd(&hist[(kk[i] >> 10) & 2047u], 1);
    __syncthreads();
    find_thr(hist, 2048, tgt2, &b_sh, &t_sh, ws);
    if (t == 0) { pre_sh = (b1 << 11) | (unsigned)b_sh; e_sh = t_sh; }
    __syncthreads();
    unsigned pre = pre_sh;
    int tgt3 = e_sh;

    // ---- level 3 (low 10 bits) ----
    hist[t] = 0; hist[t + 1024] = 0;
    __syncthreads();
    for (int i = 0; i < nk; i++)
        if ((kk[i] >> 10) == pre) atomicAdd(&hist[kk[i] & 1023u], 1);
    __syncthreads();
    find_thr(hist, 1024, tgt3, &b_sh, &t_sh, ws);
    if (t == 0) { K100_sh = (pre << 10) | (unsigned)b_sh; e_sh = t_sh; }
    __syncthreads();
    unsigned K100 = K100_sh;
    int e = e_sh;
    int g = MAXDET - e;

    // ---- collect exactly 100 keys ----
    for (int i = 0; i < nk; i++) {
        unsigned k = kk[i];
        if (k > K100) {
            int p = atomicAdd(&gcnt, 1);
            if (p < g) arr[p] = k;
        } else if (k == K100) {
            int p = atomicAdd(&ecnt, 1);
            if (p < e) arr[g + p] = k;
        }
    }
    __syncthreads();

    // ---- rank sort 100 keys descending ----
    int Smin = (S < MAXDET) ? S : MAXDET;
    if (t < Smin) {
        unsigned kt = arr[t];
        int r = 0;
        for (int j = 0; j < Smin; j++) {
            unsigned kj = arr[j];
            r += ((kj > kt) || (kj == kt && j < t)) ? 1 : 0;
        }
        srt[r] = kt;
    }
    __syncthreads();

    // outputs: [scores 100][labels 100][poses 1200][idx 100][boxes 400] = 1900 floats
    if (t < MAXDET) {
        int q = t;
        float osc = -1.0f;
        if (q < S) {
            unsigned u = srt[q];
            u = (u & 0x80000000u) ? (u ^ 0x80000000u) : ~u;
            osc = __uint_as_float(u);
        }
        if (q < out_size) out[q] = osc;
        float lab = (q < S) ? (float)(sel[q] >> 12) : -1.0f;
        if (100 + q < out_size) out[100 + q] = lab;
        float idx = (q < S) ? (float)(sel[q] & (NN - 1)) : -1.0f;
        if (1400 + q < out_size) out[1400 + q] = idx;
    }
    for (int q = t; q < 1200; q += 1024) {
        int k = q / 12, d = q % 12;
        float v = (k < S) ? g_pavg[sel[k] * 12 + d] : -1.0f;
        if (200 + q < out_size) out[200 + q] = v;
    }
    for (int q = t; q < 400; q += 1024) {
        int k = q >> 2, d = q & 3;
        float v = (k < S) ? g_bavg[sel[k] * 4 + d] : -1.0f;
        if (1500 + q < out_size) out[1500 + q] = v;
    }
}

// ---------------- K2: scan+scatter+top-11+compaction; last block runs selection ----------------
// dynamic smem layout: scnt[4096] | soff[4096] | cand[4096] (u64)
__global__ __launch_bounds__(1024) void k2_fused(const float* __restrict__ boxes,
                                                 const float* __restrict__ poses,
                                                 const float* __restrict__ cls,
                                                 float* __restrict__ out, int out_size) {
    extern __shared__ int sm[];
    int* scnt = sm;                    // cursors
    int* soff = sm + NN;               // exclusive offsets
    unsigned long long* cand = (unsigned long long*)(sm + 2 * NN);
    __shared__ int ws[32];
    __shared__ int is_last;

    int c = blockIdx.x;
    int t = threadIdx.x;
    int m = g_m[c];

    // --- phase 2: read per-row counts (zero them for next replay), scan ---
    int4 cnt4 = *(const int4*)&g_candcnt[c * NN + t * 4];
    *(int4*)&g_candcnt[c * NN + t * 4] = make_int4(0, 0, 0, 0);
    int rcnt[4] = {cnt4.x, cnt4.y, cnt4.z, cnt4.w};
    int run = rcnt[0] + rcnt[1] + rcnt[2] + rcnt[3];
    int incv = blockScanInc(run, ws);
    {
        int acc = incv - run;
#pragma unroll
        for (int u = 0; u < 4; u++) { soff[t * 4 + u] = acc; acc += rcnt[u]; }
    }
    *(int4*)&scnt[t * 4] = make_int4(0, 0, 0, 0);
    __syncthreads();

    // --- phase 3: scatter candidates into smem CSR ---
#pragma unroll
    for (int u = 0; u < 4; u++) {
        int s = t + u * 1024;
        if (s < m) {
            int slot = c * NN + s;
            float v = g_val[slot];
            if (v != 0.0f) {
                int r = g_maxcol[slot];
                int i = __float_as_int(g_saux[slot].y);
                int pos = soff[r] + atomicAdd(&scnt[r], 1);
                cand[pos] = ((unsigned long long)__float_as_uint(v) << 32) | (unsigned)i;
            }
        }
    }
    __syncthreads();

    // --- phase 4: per-row top-11 + averages ---
    int L = min(KH, m);
    bool survu[4];
#pragma unroll
    for (int u = 0; u < 4; u++) {
        int row = t * 4 + u;
        int cnt = rcnt[u];
        int used = 0;
        if (cnt > 0) {
            int off = soff[row];
            unsigned long long b[KH];
#pragma unroll
            for (int p = 0; p < KH; p++) b[p] = ~0ULL;
            for (int q = 0; q < cnt; q++) {
                unsigned long long x = cand[off + q];
#pragma unroll
                for (int p = 0; p < KH; p++) {
                    unsigned long long lo = (b[p] < x) ? b[p] : x;
                    unsigned long long hi = (b[p] < x) ? x : b[p];
                    b[p] = lo;
                    x = hi;
                }
            }
            used = min(min(cnt, KH), L);
            if (used > 0) {
                float ps[12], bs4[4];
#pragma unroll
                for (int d = 0; d < 12; d++) ps[d] = 0.0f;
#pragma unroll
                for (int d = 0; d < 4; d++) bs4[d] = 0.0f;
                for (int q = 0; q < used; q++) {
                    int a = (int)(b[q] & 0xFFFFFFFFu);
                    const float* pp = poses + (size_t)a * (CC * 12) + c * 12;
#pragma unroll
                    for (int d = 0; d < 12; d++) ps[d] += pp[d];
                    const float* bx = boxes + (size_t)a * (CC * 4) + c * 4;
#pragma unroll
                    for (int d = 0; d < 4; d++) bs4[d] += bx[d];
                }
                float den = (float)used;
                int grow = c * NN + row;
#pragma unroll
                for (int d = 0; d < 12; d++) g_pavg[grow * 12 + d] = ps[d] / den;
#pragma unroll
                for (int d = 0; d < 4; d++) g_bavg[grow * 4 + d] = bs4[d] / den;
            }
        }
        survu[u] = (used > 0);
    }
    __syncthreads();

    // --- phase 5: survivor compaction (rows ascending) + key build ---
    int srun = 0;
    int spre[4];
#pragma unroll
    for (int u = 0; u < 4; u++) {
        spre[u] = srun;
        srun += survu[u] ? 1 : 0;
    }
    int sinc = blockScanInc(srun, ws);
    int sbase = sinc - srun;
#pragma unroll
    for (int u = 0; u < 4; u++) {
        if (survu[u]) {
            int row = t * 4 + u;
            int pos = sbase + spre[u];
            g_srow[c * NN + pos] = row;
            unsigned ub = __float_as_uint(cls[row * CC + c]);
            g_skey[c * NN + pos] = ub ^ ((ub & 0x80000000u) ? 0xFFFFFFFFu : 0x80000000u);
        }
    }
    if (t == 1023) g_scount[c] = sinc;
    __syncthreads();

    // --- phase 6: last block runs global selection ---
    if (t == 0) {
        __threadfence();
        int old = atomicAdd(&g_sync, 1);
        is_last = (old == CC - 1) ? 1 : 0;
        if (is_last) __threadfence();
    }
    __syncthreads();
    if (is_last) {
        k5_body(sm /* reuse as hist[2048] */, ws, out, out_size);
        __syncthreads();
        // reset coordination state for next graph replay
        if (t < CC) g_fB[t] = 0;
        if (t == 0) g_sync = 0;
    }
}

// ---------------- launcher ----------------
extern "C" void kernel_launch(void* const* d_in, const int* in_sizes, int n_in,
                              void* d_out, int out_size) {
    (void)in_sizes; (void)n_in;
    const float* boxes = (const float*)d_in[1];
    const float* cls   = (const float*)d_in[2];
    const float* poses = (const float*)d_in[3];
    const float* conf  = (const float*)d_in[4];
    float* out = (float*)d_out;

    int smem2 = 2 * NN * (int)sizeof(int) + NN * (int)sizeof(unsigned long long) + 128;
    cudaFuncSetAttribute(k2_fused, cudaFuncAttributeMaxDynamicSharedMemorySize, smem2);

    k0_sort<<<CC, 1024>>>(cls, boxes);
    k1_pairs<<<CC * TILES_PC, 512>>>(boxes, conf);
    k2_fused<<<CC, 1024, smem2>>>(boxes, poses, cls, out, out_size);
}

// round 15
// speedup vs baseline: 1.4991x; 1.1833x over previous
#include <cuda_runtime.h>

#define CC 8
#define NN 4096
#define NC (CC*NN)
#define KH 11
#define MAXDET 100
#define XBINS 768          // x1 in [-64, 704), 1px bins
#define XOFF 64
#define K1_TILE 32
#define K1_SUB 16
#define K1_SPAN 1024
#define SKCAP 14336        // smem key staging capacity (keys)

// ---------------- scratch (device globals; no allocation) ----------------
__device__ int    g_m[CC];            // valid count per class
__device__ float4 g_sbox[NC];         // bin-sorted boxes (by slot)
__device__ float2 g_saux[NC];         // sorted aux: (area, orig idx as int bits)
__device__ int    g_rmin[NC];         // per sorted slot: min orig idx of hit (init self)
__device__ float  g_pavg[NC*12];
__device__ float  g_bavg[NC*4];
__device__ int    g_scount[CC];       // survivors per class
__device__ int    g_srow[NC];         // compacted survivor rows (ascending per class)
__device__ unsigned g_skey[NC];       // compacted survivor keys (monotone score bits)
__device__ int    g_sync;             // last-class-block counter for k5 (reset by k0)

// ---------------- shuffle-based inclusive block scan (blockDim.x == 1024) ----------------
__device__ __forceinline__ int blockScanInc(int v, int* ws) {
    const unsigned FULL = 0xFFFFFFFFu;
    int lane = threadIdx.x & 31, w = threadIdx.x >> 5;
#pragma unroll
    for (int o = 1; o < 32; o <<= 1) {
        int n = __shfl_up_sync(FULL, v, o);
        if (lane >= o) v += n;
    }
    if (lane == 31) ws[w] = v;
    __syncthreads();
    if (w == 0) {
        int s = ws[lane];
#pragma unroll
        for (int o = 1; o < 32; o <<= 1) {
            int n = __shfl_up_sync(FULL, s, o);
            if (lane >= o) s += n;
        }
        ws[lane] = s;
    }
    __syncthreads();
    int r = v + ((w > 0) ? ws[w - 1] : 0);
    __syncthreads();
    return r;
}

// ---------------- K0: per-class compact + counting sort ----------------
__global__ __launch_bounds__(1024) void k0_sort(const float* __restrict__ cls,
                                                const float* __restrict__ boxes) {
    __shared__ int hist[XBINS];
    __shared__ int sstart[XBINS];
    __shared__ int ws[32];
    int c = blockIdx.x;
    int t = threadIdx.x;

    if (c == 0 && t == 0) g_sync = 0;      // reset fusion counter each launch

    for (int b = t; b < XBINS; b += 1024) hist[b] = 0;
    __syncthreads();

    bool   myv[4];
    int    mybin[4];
    float4 mybox[4];
#pragma unroll
    for (int u = 0; u < 4; u++) {
        int a = t + u * 1024;
        float sc = cls[a * CC + c];
        myv[u] = sc > 0.5f;
        if (myv[u]) {
            mybox[u] = *(const float4*)(boxes + (size_t)a * (CC * 4) + c * 4);
            int b = __float2int_rd(mybox[u].x) + XOFF;
            b = max(0, min(XBINS - 1, b));
            mybin[u] = b;
            atomicAdd(&hist[b], 1);
        }
    }
    __syncthreads();

    int hv = (t < XBINS) ? hist[t] : 0;
    int inc = blockScanInc(hv, ws);
    if (t < XBINS) sstart[t] = inc - hv;
    if (t == XBINS - 1) g_m[c] = inc;
    __syncthreads();
    for (int b = t; b < XBINS; b += 1024) hist[b] = 0;
    __syncthreads();

#pragma unroll
    for (int u = 0; u < 4; u++) {
        if (myv[u]) {
            int a = t + u * 1024;
            int pos = sstart[mybin[u]] + atomicAdd(&hist[mybin[u]], 1);
            int slot = c * NN + pos;
            float4 b = mybox[u];
            g_sbox[slot] = b;
            g_saux[slot] = make_float2((b.z - b.x + 1.0f) * (b.w - b.y + 1.0f),
                                       __int_as_float(a));
            g_rmin[slot] = a;   // self hit baseline
        }
    }
}

// ---------------- K1: symmetric forward pair scan, 16 sub-threads per anchor ----------------
__global__ __launch_bounds__(512) void k1_pairs() {
    __shared__ float4 tb[K1_SPAN];
    __shared__ float2 ta[K1_SPAN];

    int c  = blockIdx.x >> 7;           // 128 tiles per class
    int S0 = (blockIdx.x & 127) * K1_TILE;
    int m  = g_m[c];
    if (S0 >= m) return;

    for (int k = threadIdx.x; k < K1_SPAN; k += 512) {
        int s = S0 + k;
        if (s < m) {
            tb[k] = g_sbox[c * NN + s];
            ta[k] = g_saux[c * NN + s];
        } else {
            tb[k] = make_float4(3.0e38f, 0.0f, -10.0f, -10.0f); // x1=+inf sentinel
            ta[k] = make_float2(1.0f, __int_as_float(0));
        }
    }
    __syncthreads();

    int ai  = threadIdx.x & (K1_TILE - 1);     // anchor within tile
    int sub = threadIdx.x >> 5;                // 0..15
    int s = S0 + ai;
    if (s >= m) return;

    float4 a    = tb[ai];
    float areaA = ta[ai].x;
    int   origI = __float_as_int(ta[ai].y);
    float limit = a.z + 2.0f;   // (x2_s + 1) + 1px bin-order slop

    for (int ts = ai + 1 + sub; ; ts += K1_SUB) {
        float4 b; float2 ax;
        if (ts < K1_SPAN) {
            b  = tb[ts];
            ax = ta[ts];
        } else {
            int gs = S0 + ts;
            if (gs >= m) break;
            b  = g_sbox[c * NN + gs];
            ax = g_saux[c * NN + gs];
        }
        if (b.x >= limit) break;

        float x1 = fmaxf(a.x, b.x);
        float y1 = fmaxf(a.y, b.y);
        float x2 = fminf(a.z, b.z);
        float y2 = fminf(a.w, b.w);
        float w = x2 - x1 + 1.0f;
        float h = y2 - y1 + 1.0f;
        float inter = w * h;
        float den = areaA + ax.x - inter;
        if (w > 0.0f && h > 0.0f && inter > 0.5f * den) {
            int origJ = __float_as_int(ax.y);
            atomicMin(&g_rmin[c * NN + s], origJ);
            atomicMin(&g_rmin[c * NN + S0 + ts], origI);
        }
    }
}

// ---------------- k5 body: smem-staged keys, 3-pass radix select (one block) ----------------
__device__ __forceinline__ void find_thr(const int* hist, int nbins, int target,
                                         volatile int* out_b, volatile int* out_t,
                                         int* ws) {
    int t = threadIdx.x;
    if (t == 0) { *out_b = 0; *out_t = 0; }
    __syncthreads();
    if (nbins == 2048) {
        int b1 = 2047 - 2 * t;
        int b0 = b1 - 1;
        int h1 = hist[b1], h0 = hist[b0];
        int inc = blockScanInc(h1 + h0, ws);     // suffix sum at b0
        int suf0 = inc;
        int suf1 = inc - h0;
        if (suf1 >= target && suf1 - h1 < target) { *out_b = b1; *out_t = target - (suf1 - h1); }
        if (suf0 >= target && suf0 - h0 < target) { *out_b = b0; *out_t = target - (suf0 - h0); }
    } else {
        int b = 1023 - t;
        int h = hist[b];
        int inc = blockScanInc(h, ws);
        if (inc >= target && inc - h < target) { *out_b = b; *out_t = target - (inc - h); }
    }
    __syncthreads();
}

__device__ void k5_body(int* sm, int* ws, float* __restrict__ out, int out_size) {
    int* hist = sm;                            // [2048] ints
    unsigned* skeys = (unsigned*)(sm + 2048);  // [SKCAP] staged survivor keys
    __shared__ int cb[CC + 1];
    __shared__ int sel[MAXDET];
    __shared__ unsigned arr[MAXDET];
    __shared__ unsigned srt[MAXDET];
    __shared__ volatile int b_sh, t_sh;
    __shared__ int t1_sh, b1_sh, e_sh, gcnt, ecnt;
    __shared__ unsigned pre_sh, K100_sh;

    int t = threadIdx.x;
    if (t == 0) {
        int s = 0;
        for (int c = 0; c < CC; c++) { cb[c] = s; s += g_scount[c]; }
        cb[CC] = s;
        gcnt = 0; ecnt = 0;
    }
    __syncthreads();
    int S = cb[CC];

    // sel[q] = flat id of q-th survivor (class-major, rows ascending)
    if (t < MAXDET && t < S) {
        int c = 0;
        while (c < CC - 1 && t >= cb[c + 1]) c++;
        sel[t] = c * NN + g_srow[c * NN + (t - cb[c])];
    }

    // ---- stage keys into smem (coalesced, once) + zero hist ----
    hist[t] = 0; hist[t + 1024] = 0;
#pragma unroll 1
    for (int c = 0; c < CC; c++) {
        int b0 = cb[c], cnt = cb[c + 1] - b0;
        for (int q = t; q < cnt; q += 1024) {
            int f = b0 + q;
            if (f < SKCAP) skeys[f] = g_skey[c * NN + q];
        }
    }
    __syncthreads();

    // key fetch helper (smem fast path, global fallback for f >= SKCAP)
    auto getkey = [&](int f) -> unsigned {
        if (f < SKCAP) return skeys[f];
        int c = 0;
        while (c < CC - 1 && f >= cb[c + 1]) c++;
        return g_skey[c * NN + (f - cb[c])];
    };

    // ---- radix-select level 1 (top 11 bits) ----
    for (int f = t; f < S; f += 1024) atomicAdd(&hist[getkey(f) >> 21], 1);
    __syncthreads();
    find_thr(hist, 2048, MAXDET, &b_sh, &t_sh, ws);
    if (t == 0) { b1_sh = b_sh; t1_sh = t_sh; }
    __syncthreads();
    unsigned b1 = (unsigned)b1_sh;
    int tgt2 = t1_sh;

    // ---- level 2 (next 11 bits) ----
    hist[t] = 0; hist[t + 1024] = 0;
    __syncthreads();
    for (int f = t; f < S; f += 1024) {
        unsigned k = getkey(f);
        if ((k >> 21) == b1) atomicAdd(&hist[(k >> 10) & 2047u], 1);
    }
    __syncthreads();
    find_thr(hist, 2048, tgt2, &b_sh, &t_sh, ws);
    if (t == 0) { pre_sh = (b1 << 11) | (unsigned)b_sh; e_sh = t_sh; }
    __syncthreads();
    unsigned pre = pre_sh;
    int tgt3 = e_sh;

    // ---- level 3 (low 10 bits) ----
    hist[t] = 0; hist[t + 1024] = 0;
    __syncthreads();
    for (int f = t; f < S; f += 1024) {
        unsigned k = getkey(f);
        if ((k >> 10) == pre) atomicAdd(&hist[k & 1023u], 1);
    }
    __syncthreads();
    find_thr(hist, 1024, tgt3, &b_sh, &t_sh, ws);
    if (t == 0) { K100_sh = (pre << 10) | (unsigned)b_sh; e_sh = t_sh; }
    __syncthreads();
    unsigned K100 = K100_sh;
    int e = e_sh;
    int g = MAXDET - e;

    // ---- collect exactly 100 keys ----
    for (int f = t; f < S; f += 1024) {
        unsigned k = getkey(f);
        if (k > K100) {
            int p = atomicAdd(&gcnt, 1);
            if (p < g) arr[p] = k;
        } else if (k == K100) {
            int p = atomicAdd(&ecnt, 1);
            if (p < e) arr[g + p] = k;
        }
    }
    __syncthreads();

    // ---- rank sort 100 keys descending ----
    int Smin = (S < MAXDET) ? S : MAXDET;
    if (t < Smin) {
        unsigned kt = arr[t];
        int r = 0;
        for (int j = 0; j < Smin; j++) {
            unsigned kj = arr[j];
            r += ((kj > kt) || (kj == kt && j < t)) ? 1 : 0;
        }
        srt[r] = kt;
    }
    __syncthreads();

    // outputs: [scores 100][labels 100][poses 1200][idx 100][boxes 400] = 1900 floats
    if (t < MAXDET) {
        int q = t;
        float osc = -1.0f;
        if (q < S) {
            unsigned u = srt[q];
            u = (u & 0x80000000u) ? (u ^ 0x80000000u) : ~u;
            osc = __uint_as_float(u);
        }
        if (q < out_size) out[q] = osc;
        float lab = (q < S) ? (float)(sel[q] >> 12) : -1.0f;
        if (100 + q < out_size) out[100 + q] = lab;
        float idx = (q < S) ? (float)(sel[q] & (NN - 1)) : -1.0f;
        if (1400 + q < out_size) out[1400 + q] = idx;
    }
    for (int q = t; q < 1200; q += 1024) {
        int k = q / 12, d = q % 12;
        float v = (k < S) ? g_pavg[sel[k] * 12 + d] : -1.0f;
        if (200 + q < out_size) out[200 + q] = v;
    }
    for (int q = t; q < 400; q += 1024) {
        int k = q >> 2, d = q & 3;
        float v = (k < S) ? g_bavg[sel[k] * 4 + d] : -1.0f;
        if (1500 + q < out_size) out[1500 + q] = v;
    }
}

// ---------------- K2: fused values+scan+scatter+top-11+compaction, last block runs k5 ----------------
// dynamic smem layout: scnt[4096] | soff[4096] | cand[4096] (u64)
__global__ __launch_bounds__(1024) void k2_fused(const float* __restrict__ boxes,
                                                 const float* __restrict__ conf,
                                                 const float* __restrict__ poses,
                                                 const float* __restrict__ cls,
                                                 float* __restrict__ out, int out_size) {
    extern __shared__ int sm[];
    int* scnt = sm;                    // counts, later cursors
    int* soff = sm + NN;               // exclusive offsets
    unsigned long long* cand = (unsigned long long*)(sm + 2 * NN);
    __shared__ int ws[32];
    __shared__ int is_last;

    int c = blockIdx.x;
    int t = threadIdx.x;
    int m = g_m[c];

    *(int4*)&scnt[t * 4] = make_int4(0, 0, 0, 0);
    __syncthreads();

    // --- phase 1: per-slot winner value; count per target row (smem atomics) ---
    float vv[4];
    int   vi[4], vr[4];
    bool  has[4];
#pragma unroll
    for (int u = 0; u < 4; u++) {
        has[u] = false;
        int s = t + u * 1024;
        if (s < m) {
            int slot = c * NN + s;
            int r = g_rmin[slot];
            int i = __float_as_int(g_saux[slot].y);
            if (r != i) {
                float4 bi = g_sbox[slot];
                float4 br = *(const float4*)(boxes + (size_t)r * (CC * 4) + c * 4);
                float x1 = fmaxf(bi.x, br.x);
                float y1 = fmaxf(bi.y, br.y);
                float x2 = fminf(bi.z, br.z);
                float y2 = fminf(bi.w, br.w);
                float w = x2 - x1 + 1.0f;
                float h = y2 - y1 + 1.0f;
                float inter = w * h;
                float areaI = (bi.z - bi.x + 1.0f) * (bi.w - bi.y + 1.0f);
                float areaR = (br.z - br.x + 1.0f) * (br.w - br.y + 1.0f);
                float den = areaI + areaR - inter;
                float ov = (den == 0.0f) ? 0.0f : inter / den;
                if (w <= 0.0f || h <= 0.0f) ov = 0.0f;
                float v = (1.0f - ov) * conf[i * CC + c];
                if (v != 0.0f) {
                    vv[u] = v; vi[u] = i; vr[u] = r; has[u] = true;
                    atomicAdd(&scnt[r], 1);
                }
            }
        }
    }
    __syncthreads();

    // --- phase 2: exclusive scan over 4096 row counts ---
    int rcnt[4];
    int run = 0;
    int pre[4];
#pragma unroll
    for (int u = 0; u < 4; u++) {
        rcnt[u] = scnt[t * 4 + u];
        pre[u] = run;
        run += rcnt[u];
    }
    int incv = blockScanInc(run, ws);
    int base = incv - run;
#pragma unroll
    for (int u = 0; u < 4; u++) soff[t * 4 + u] = base + pre[u];
    __syncthreads();
    *(int4*)&scnt[t * 4] = make_int4(0, 0, 0, 0);
    __syncthreads();

    // --- phase 3: scatter candidates into smem CSR ---
#pragma unroll
    for (int u = 0; u < 4; u++) {
        if (has[u]) {
            int r = vr[u];
            int pos = soff[r] + atomicAdd(&scnt[r], 1);
            cand[pos] = ((unsigned long long)__float_as_uint(vv[u]) << 32) | (unsigned)vi[u];
        }
    }
    __syncthreads();

    // --- phase 4: per-row top-11 + averages ---
    int L = min(KH, m);
    bool survu[4];
#pragma unroll
    for (int u = 0; u < 4; u++) {
        int row = t * 4 + u;
        int cnt = rcnt[u];
        int used = 0;
        if (cnt > 0) {
            int off = soff[row];
            unsigned long long b[KH];
#pragma unroll
            for (int p = 0; p < KH; p++) b[p] = ~0ULL;
            for (int q = 0; q < cnt; q++) {
                unsigned long long x = cand[off + q];
#pragma unroll
                for (int p = 0; p < KH; p++) {
                    unsigned long long lo = (b[p] < x) ? b[p] : x;
                    unsigned long long hi = (b[p] < x) ? x : b[p];
                    b[p] = lo;
                    x = hi;
                }
            }
            used = min(min(cnt, KH), L);
            if (used > 0) {
                float ps[12], bs4[4];
#pragma unroll
                for (int d = 0; d < 12; d++) ps[d] = 0.0f;
#pragma unroll
                for (int d = 0; d < 4; d++) bs4[d] = 0.0f;
                for (int q = 0; q < used; q++) {
                    int a = (int)(b[q] & 0xFFFFFFFFu);
                    const float* pp = poses + (size_t)a * (CC * 12) + c * 12;
#pragma unroll
                    for (int d = 0; d < 12; d++) ps[d] += pp[d];
                    const float* bx = boxes + (size_t)a * (CC * 4) + c * 4;
#pragma unroll
                    for (int d = 0; d < 4; d++) bs4[d] += bx[d];
                }
                float den = (float)used;
                int grow = c * NN + row;
#pragma unroll
                for (int d = 0; d < 12; d++) g_pavg[grow * 12 + d] = ps[d] / den;
#pragma unroll
                for (int d = 0; d < 4; d++) g_bavg[grow * 4 + d] = bs4[d] / den;
            }
        }
        survu[u] = (used > 0);
    }
    __syncthreads();

    // --- phase 5: survivor compaction (rows ascending) + key build ---
    int srun = 0;
    int spre[4];
#pragma unroll
    for (int u = 0; u < 4; u++) {
        spre[u] = srun;
        srun += survu[u] ? 1 : 0;
    }
    int sinc = blockScanInc(srun, ws);
    int sbase = sinc - srun;
#pragma unroll
    for (int u = 0; u < 4; u++) {
        if (survu[u]) {
            int row = t * 4 + u;
            int pos = sbase + spre[u];
            g_srow[c * NN + pos] = row;
            unsigned ub = __float_as_uint(cls[row * CC + c]);
            g_skey[c * NN + pos] = ub ^ ((ub & 0x80000000u) ? 0xFFFFFFFFu : 0x80000000u);
        }
    }
    if (t == 1023) g_scount[c] = sinc;
    __syncthreads();

    // --- phase 6: last block runs global selection (threadFenceReduction pattern) ---
    if (t == 0) {
        __threadfence();
        int old = atomicAdd(&g_sync, 1);
        is_last = (old == CC - 1) ? 1 : 0;
        if (is_last) __threadfence();
    }
    __syncthreads();
    if (is_last) {
        k5_body(sm, ws, out, out_size);
    }
}

// ---------------- launcher ----------------
extern "C" void kernel_launch(void* const* d_in, const int* in_sizes, int n_in,
                              void* d_out, int out_size) {
    (void)in_sizes; (void)n_in;
    const float* boxes = (const float*)d_in[1];
    const float* cls   = (const float*)d_in[2];
    const float* poses = (const float*)d_in[3];
    const float* conf  = (const float*)d_in[4];
    float* out = (float*)d_out;

    int smem2 = 2 * NN * (int)sizeof(int) + NN * (int)sizeof(unsigned long long) + 128;
    cudaFuncSetAttribute(k2_fused, cudaFuncAttributeMaxDynamicSharedMemorySize, smem2);

    k0_sort<<<CC, 1024>>>(cls, boxes);
    k1_pairs<<<CC * 128, 512>>>();
    k2_fused<<<CC, 1024, smem2>>>(boxes, conf, poses, cls, out, out_size);
}